// round 11
// baseline (speedup 1.0000x reference)
#include <cuda_runtime.h>

// MS-SSIM (windows 5/11/17), fused separable, f32x2-packed, 32x64 tile,
// merged variance planes + double-buffered H.
// out = 0.25 + sum_k clip(ssim_k, -1, 1) / 12

#define RAD 8
#define S 48            // smem tile cols: 32 + 2*RAD
#define TR 80           // smem tile rows: 64 + 2*RAD
#define NT 512
#define SSIM_C1 (0.01f*0.01f)
#define SSIM_C2 (0.03f*0.03f)

struct Weights {
    float2 h5[5],  v5[5];      // dup pairs (w,w); v normalized by center
    float2 h11[11], v11[11];
    float2 h17[17], v17[17];
};
__device__  Weights g_stage;
__constant__ Weights c_w;

union F2U { float2 f; unsigned long long u; };

__device__ __forceinline__ float2 ffma2(float2 a, float2 b, float2 c) {
    F2U A, B, C, D; A.f = a; B.f = b; C.f = c;
    asm("fma.rn.f32x2 %0, %1, %2, %3;" : "=l"(D.u) : "l"(A.u), "l"(B.u), "l"(C.u));
    return D.f;
}
__device__ __forceinline__ float2 fmul2(float2 a, float2 b) {
    F2U A, B, D; A.f = a; B.f = b;
    asm("mul.rn.f32x2 %0, %1, %2;" : "=l"(D.u) : "l"(A.u), "l"(B.u));
    return D.f;
}

__device__ __forceinline__ void build_tables(const float* g, int R,
                                             float2* h, float2* v) {
    const int K = 2*R + 1;
    float ctr = g[R*K + R];
    for (int t = 0; t < K; ++t) {
        float hv = g[R*K + t];
        float vv = g[t*K + R] / ctr;
        h[t] = make_float2(hv, hv);
        v[t] = make_float2(vv, vv);
    }
}

__global__ void prep_weights(const float* g5, const float* g11, const float* g17) {
    if (threadIdx.x != 0) return;
    build_tables(g5,  2, g_stage.h5,  g_stage.v5);
    build_tables(g11, 5, g_stage.h11, g_stage.v11);
    build_tables(g17, 8, g_stage.h17, g_stage.v17);
}

template<int R>
__device__ __forceinline__ void wpass(const float4* __restrict__ sT4,
                                      float2* __restrict__ Hmu,
                                      float2* __restrict__ Hmp,
                                      int tid, float acc[4])
{
    constexpr int K    = 2*R + 1;
    constexpr int ROWS = 64 + 2*R;
    constexpr int R0   = RAD - R;
    constexpr int NI   = ROWS * 16;
    constexpr int ODD  = (R & 1);
    constexpr int L    = (2*R + 2 + ODD + 1) / 2;   // float4 loads/item

    const float2* wh = (R == 2) ? c_w.h5 : (R == 5) ? c_w.h11 : c_w.h17;
    const float2* wv = (R == 2) ? c_w.v5 : (R == 5) ? c_w.v11 : c_w.v17;

    // ---- horizontal: 2 output cols/item, dense float4 sliding loads ----
    #pragma unroll
    for (int it = 0; it < 3; ++it) {
        int i = tid + NT * it;
        if (i < NI) {
            int row = R0 + (i >> 4);
            int cg  = i & 15;
            const float4* p4 = sT4 + ((row * S + 2*cg + RAD - R - ODD) >> 1);
            float2 mu0 = {0,0}, mu1 = {0,0}, mp0 = {0,0}, mp1 = {0,0};

            auto tap = [&](float2 v, int t0) {
                if (t0 >= 0 && t0 <= K) {            // compile-time after unroll
                    float2 sq = fmul2(v, v);
                    float2 pp = make_float2(sq.x + sq.y, v.x * v.y);
                    if (t0 < K) {
                        float2 w = wh[t0];
                        mu0 = ffma2(w, v,  mu0);
                        mp0 = ffma2(w, pp, mp0);
                    }
                    if (t0 >= 1) {
                        float2 w = wh[t0 - 1];
                        mu1 = ffma2(w, v,  mu1);
                        mp1 = ffma2(w, pp, mp1);
                    }
                }
            };

            #pragma unroll
            for (int l = 0; l < L; ++l) {
                float4 q = p4[l];                    // LDS.128, dense
                tap(make_float2(q.x, q.y), 2*l - ODD);
                tap(make_float2(q.z, q.w), 2*l - ODD + 1);
            }

            int o = row * 32 + 2*cg;
            *reinterpret_cast<float4*>(Hmu + o) = make_float4(mu0.x, mu0.y, mu1.x, mu1.y);
            *reinterpret_cast<float4*>(Hmp + o) = make_float4(mp0.x, mp0.y, mp1.x, mp1.y);
        }
    }
    __syncthreads();

    // ---- vertical: 1 col x 4 rows per thread ----
    const int col = tid & 31;
    const int ty  = tid >> 5;                        // 0..15 -> rows 4ty..4ty+3
    float2 amu[4] = {}; float2 amp[4] = {};
    const int ybase = RAD + 4*ty - R;
    #pragma unroll
    for (int yy = 0; yy < 4 + 2*R; ++yy) {
        int o = (ybase + yy) * 32 + col;
        float2 hmu = Hmu[o];
        float2 hmp = Hmp[o];
        #pragma unroll
        for (int j = 0; j < 4; ++j) {
            int t = yy - j;
            if (t >= 0 && t < K) {
                float2 wp = wv[t];
                amu[j] = ffma2(wp, hmu, amu[j]);
                amp[j] = ffma2(wp, hmp, amp[j]);
            }
        }
    }

    #pragma unroll
    for (int j = 0; j < 4; ++j) {
        float2 m2 = fmul2(amu[j], amu[j]);
        float q    = m2.x + m2.y;                    // mu1^2 + mu2^2
        float mu12 = amu[j].x * amu[j].y;
        float ssum = amp[j].x - q;                   // s1sq + s2sq (variance >= 0)
        float s12  = amp[j].y - mu12;
        float num = (2.f*mu12 + SSIM_C1) * (2.f*s12 + SSIM_C2);
        float den = (q + SSIM_C1) * (ssum + SSIM_C2);
        float v = __fdividef(num, den);
        acc[j] += fminf(1.f, fmaxf(-1.f, v));
    }
    // no trailing sync: next window writes the OTHER H buffer; its
    // horizontal->vertical barrier orders this window's readers.
}

__global__ __launch_bounds__(NT, 2)
void mssim_kernel(const float* __restrict__ b1,
                  const float* __restrict__ b2,
                  float* __restrict__ out)
{
    // dynamic smem: sT 30720 | HmuA 20480 | HmpA 20480 | HmuB 20480 | HmpB 20480
    extern __shared__ __align__(16) char smbuf[];
    float2* sT   = reinterpret_cast<float2*>(smbuf);
    float2* HmuA = reinterpret_cast<float2*>(smbuf + 30720);
    float2* HmpA = reinterpret_cast<float2*>(smbuf + 51200);
    float2* HmuB = reinterpret_cast<float2*>(smbuf + 71680);
    float2* HmpB = reinterpret_cast<float2*>(smbuf + 92160);

    const int tid = threadIdx.x;
    const int plane = blockIdx.z;
    const long base = (long)plane * (512 * 512);
    const int ox = blockIdx.x * 32 - RAD;
    const int oy = blockIdx.y * 64 - RAD;

    #pragma unroll
    for (int sIt = 0; sIt < 8; ++sIt) {
        int i = tid + NT * sIt;                // need 0..3839
        if (i < TR * S) {
            int ly = i / S;
            int lx = i - ly * S;
            int gy = oy + ly;
            int gx = ox + lx;
            float v1 = 0.f, v2 = 0.f;
            if (gy >= 0 && gy < 512 && gx >= 0 && gx < 512) {
                long idx = base + (long)gy * 512 + gx;
                v1 = b1[idx];
                v2 = b2[idx];
            }
            sT[i] = make_float2(v1, v2);
        }
    }
    __syncthreads();

    const float4* sT4 = reinterpret_cast<const float4*>(smbuf);

    float acc[4] = {0.f, 0.f, 0.f, 0.f};
    wpass<2>(sT4, HmuA, HmpA, tid, acc);
    wpass<5>(sT4, HmuB, HmpB, tid, acc);
    wpass<8>(sT4, HmuA, HmpA, tid, acc);

    const int tx = tid & 31;
    const int ty = tid >> 5;
    const int gx = blockIdx.x * 32 + tx;
    #pragma unroll
    for (int j = 0; j < 4; ++j) {
        int gy = blockIdx.y * 64 + ty * 4 + j;
        out[base + (long)gy * 512 + gx] = 0.25f + acc[j] * (1.0f / 12.0f);
    }
}

extern "C" void kernel_launch(void* const* d_in, const int* in_sizes, int n_in,
                              void* d_out, int out_size) {
    const float* b1 = (const float*)d_in[0];
    const float* b2 = (const float*)d_in[1];

    prep_weights<<<1, 32>>>((const float*)d_in[2], (const float*)d_in[3],
                            (const float*)d_in[4]);
    void* stage_ptr = nullptr;
    cudaGetSymbolAddress(&stage_ptr, g_stage);
    cudaMemcpyToSymbolAsync(c_w, stage_ptr, sizeof(Weights), 0,
                            cudaMemcpyDeviceToDevice, 0);

    static bool attr_set = false;
    if (!attr_set) {
        cudaFuncSetAttribute(mssim_kernel,
                             cudaFuncAttributeMaxDynamicSharedMemorySize, 112640);
        attr_set = true;
    }

    dim3 grid(512 / 32, 512 / 64, 96);     // 16 x 8 x 96
    mssim_kernel<<<grid, NT, 112640>>>(b1, b2, (float*)d_out);
}

// round 12
// speedup vs baseline: 1.5981x; 1.5981x over previous
#include <cuda_runtime.h>

// MS-SSIM (windows 5/11/17), fused separable, f32x2-packed, 32x64 tile.
// Merged (sumsq, cross) H plane, single-buffered.
// out = 0.25 + sum_k clip(ssim_k, -1, 1) / 12

#define RAD 8
#define S 48            // smem tile cols: 32 + 2*RAD
#define TR 80           // smem tile rows: 64 + 2*RAD
#define NT 512
#define SSIM_C1 (0.01f*0.01f)
#define SSIM_C2 (0.03f*0.03f)

struct Weights {
    // h: dup pairs (w,w); hp: shifted pairs (w[t], w[t-1]); v: dup pairs, normalized
    float2 h5[5],  hp5[7],  v5[5];
    float2 h11[11], hp11[13], v11[11];
    float2 h17[17], hp17[19], v17[17];
};
__device__  Weights g_stage;
__constant__ Weights c_w;

union F2U { float2 f; unsigned long long u; };

__device__ __forceinline__ float2 ffma2(float2 a, float2 b, float2 c) {
    F2U A, B, C, D; A.f = a; B.f = b; C.f = c;
    asm("fma.rn.f32x2 %0, %1, %2, %3;" : "=l"(D.u) : "l"(A.u), "l"(B.u), "l"(C.u));
    return D.f;
}
__device__ __forceinline__ float2 fmul2(float2 a, float2 b) {
    F2U A, B, D; A.f = a; B.f = b;
    asm("mul.rn.f32x2 %0, %1, %2;" : "=l"(D.u) : "l"(A.u), "l"(B.u));
    return D.f;
}

__device__ __forceinline__ void build_tables(const float* g, int R,
                                             float2* h, float2* hp, float2* v) {
    const int K = 2*R + 1;
    float hv[17], vv[17];
    float ctr = g[R*K + R];
    for (int t = 0; t < K; ++t) {
        hv[t] = g[R*K + t];
        vv[t] = g[t*K + R] / ctr;
    }
    for (int t = 0; t < K; ++t) {
        h[t] = make_float2(hv[t], hv[t]);
        v[t] = make_float2(vv[t], vv[t]);
    }
    for (int t = 0; t <= K + 1; ++t) {   // shifted pair table, zero-padded
        float a = (t <= K-1) ? hv[t] : 0.f;
        float b = (t >= 1 && t <= K) ? hv[t-1] : 0.f;
        hp[t] = make_float2(a, b);
    }
}

__global__ void prep_weights(const float* g5, const float* g11, const float* g17) {
    if (threadIdx.x != 0) return;
    build_tables(g5,  2, g_stage.h5,  g_stage.hp5,  g_stage.v5);
    build_tables(g11, 5, g_stage.h11, g_stage.hp11, g_stage.v11);
    build_tables(g17, 8, g_stage.h17, g_stage.hp17, g_stage.v17);
}

template<int R>
__device__ __forceinline__ void wpass(const float4* __restrict__ sT4,
                                      float2* __restrict__ Hmu,
                                      float2* __restrict__ Hmp,
                                      int tid, float acc[4])
{
    constexpr int K    = 2*R + 1;
    constexpr int ROWS = 64 + 2*R;
    constexpr int R0   = RAD - R;
    constexpr int NI   = ROWS * 16;
    constexpr int ODD  = ((RAD - R) & 1);
    constexpr int L    = (2*R + 2 + ODD + 1) / 2;   // float4 loads/item

    const float2* wh = (R == 2) ? c_w.h5  : (R == 5) ? c_w.h11  : c_w.h17;
    const float2* hp = (R == 2) ? c_w.hp5 : (R == 5) ? c_w.hp11 : c_w.hp17;
    const float2* wv = (R == 2) ? c_w.v5  : (R == 5) ? c_w.v11  : c_w.v17;

    // ---- horizontal: 2 output cols/item, dense float4 sliding loads ----
    #pragma unroll
    for (int it = 0; it < 3; ++it) {
        int i = tid + NT * it;
        if (i < NI) {
            int row = R0 + (i >> 4);
            int cg  = i & 15;
            const float4* p4 = sT4 + ((row * S + 2*cg + RAD - R - ODD) >> 1);
            float2 mu0 = {0,0}, mu1 = {0,0}, mm0 = {0,0}, mm1 = {0,0};
            float2 c01 = {0,0};

            auto tap = [&](float2 v, int t0) {
                if (t0 >= 0 && t0 <= K) {            // compile-time after unroll
                    float2 sq = fmul2(v, v);
                    float  pc = v.x * v.y;
                    float2 pcd = make_float2(pc, pc);
                    if (t0 < K) {
                        float2 w = wh[t0];
                        mu0 = ffma2(w, v,  mu0);
                        mm0 = ffma2(w, sq, mm0);
                    }
                    if (t0 >= 1) {
                        float2 w = wh[t0 - 1];
                        mu1 = ffma2(w, v,  mu1);
                        mm1 = ffma2(w, sq, mm1);
                    }
                    c01 = ffma2(hp[t0], pcd, c01);   // (cross0, cross1)
                }
            };

            #pragma unroll
            for (int l = 0; l < L; ++l) {
                float4 q = p4[l];                    // LDS.128, dense
                tap(make_float2(q.x, q.y), 2*l - ODD);
                tap(make_float2(q.z, q.w), 2*l - ODD + 1);
            }

            int o = row * 32 + 2*cg;
            *reinterpret_cast<float4*>(Hmu + o) = make_float4(mu0.x, mu0.y, mu1.x, mu1.y);
            // merge ONCE at store: (sumsq, cross) per column
            *reinterpret_cast<float4*>(Hmp + o) =
                make_float4(mm0.x + mm0.y, c01.x, mm1.x + mm1.y, c01.y);
        }
    }
    __syncthreads();

    // ---- vertical: 1 col x 4 rows per thread, 2 packed planes ----
    const int col = tid & 31;
    const int ty  = tid >> 5;                        // 0..15 -> rows 4ty..4ty+3
    float2 amu[4] = {}; float2 amp[4] = {};
    const int ybase = RAD + 4*ty - R;
    #pragma unroll
    for (int yy = 0; yy < 4 + 2*R; ++yy) {
        int o = (ybase + yy) * 32 + col;
        float2 hmu = Hmu[o];
        float2 hmp = Hmp[o];
        #pragma unroll
        for (int j = 0; j < 4; ++j) {
            int t = yy - j;
            if (t >= 0 && t < K) {
                float2 wp = wv[t];
                amu[j] = ffma2(wp, hmu, amu[j]);
                amp[j] = ffma2(wp, hmp, amp[j]);
            }
        }
    }

    #pragma unroll
    for (int j = 0; j < 4; ++j) {
        float2 m2 = fmul2(amu[j], amu[j]);
        float q    = m2.x + m2.y;                    // mu1^2 + mu2^2
        float mu12 = amu[j].x * amu[j].y;
        float ssum = amp[j].x - q;                   // s1sq + s2sq (variances >= 0)
        float s12  = amp[j].y - mu12;
        float num = (2.f*mu12 + SSIM_C1) * (2.f*s12 + SSIM_C2);
        float den = (q + SSIM_C1) * (ssum + SSIM_C2);
        float v = __fdividef(num, den);
        acc[j] += fminf(1.f, fmaxf(-1.f, v));
    }
    __syncthreads();   // single H buffer is reused by next window
}

__global__ __launch_bounds__(NT, 2)
void mssim_kernel(const float* __restrict__ b1,
                  const float* __restrict__ b2,
                  float* __restrict__ out)
{
    // dynamic smem: sT 30720 | Hmu 20480 | Hmp 20480 = 71680 B
    extern __shared__ __align__(16) char smbuf[];
    float2* sT  = reinterpret_cast<float2*>(smbuf);
    float2* Hmu = reinterpret_cast<float2*>(smbuf + 30720);
    float2* Hmp = reinterpret_cast<float2*>(smbuf + 51200);

    const int tid = threadIdx.x;
    const int plane = blockIdx.z;
    const long base = (long)plane * (512 * 512);
    const int ox = blockIdx.x * 32 - RAD;
    const int oy = blockIdx.y * 64 - RAD;

    #pragma unroll
    for (int sIt = 0; sIt < 8; ++sIt) {
        int i = tid + NT * sIt;                // need 0..3839
        if (i < TR * S) {
            int ly = i / S;
            int lx = i - ly * S;
            int gy = oy + ly;
            int gx = ox + lx;
            float v1 = 0.f, v2 = 0.f;
            if (gy >= 0 && gy < 512 && gx >= 0 && gx < 512) {
                long idx = base + (long)gy * 512 + gx;
                v1 = b1[idx];
                v2 = b2[idx];
            }
            sT[i] = make_float2(v1, v2);
        }
    }
    __syncthreads();

    const float4* sT4 = reinterpret_cast<const float4*>(smbuf);

    float acc[4] = {0.f, 0.f, 0.f, 0.f};
    wpass<2>(sT4, Hmu, Hmp, tid, acc);
    wpass<5>(sT4, Hmu, Hmp, tid, acc);
    wpass<8>(sT4, Hmu, Hmp, tid, acc);

    const int tx = tid & 31;
    const int ty = tid >> 5;
    const int gx = blockIdx.x * 32 + tx;
    #pragma unroll
    for (int j = 0; j < 4; ++j) {
        int gy = blockIdx.y * 64 + ty * 4 + j;
        out[base + (long)gy * 512 + gx] = 0.25f + acc[j] * (1.0f / 12.0f);
    }
}

extern "C" void kernel_launch(void* const* d_in, const int* in_sizes, int n_in,
                              void* d_out, int out_size) {
    const float* b1 = (const float*)d_in[0];
    const float* b2 = (const float*)d_in[1];

    prep_weights<<<1, 32>>>((const float*)d_in[2], (const float*)d_in[3],
                            (const float*)d_in[4]);
    void* stage_ptr = nullptr;
    cudaGetSymbolAddress(&stage_ptr, g_stage);
    cudaMemcpyToSymbolAsync(c_w, stage_ptr, sizeof(Weights), 0,
                            cudaMemcpyDeviceToDevice, 0);

    static bool attr_set = false;
    if (!attr_set) {
        cudaFuncSetAttribute(mssim_kernel,
                             cudaFuncAttributeMaxDynamicSharedMemorySize, 71680);
        attr_set = true;
    }

    dim3 grid(512 / 32, 512 / 64, 96);     // 16 x 8 x 96
    mssim_kernel<<<grid, NT, 71680>>>(b1, b2, (float*)d_out);
}

// round 17
// speedup vs baseline: 1.7743x; 1.1103x over previous
#include <cuda_runtime.h>

// MS-SSIM (windows 5/11/17), fused separable, f32x2-packed, 32x64 tile.
// Sum/difference transform: convolve (u,d)=(v1+v2, v1-v2) and (u^2,d^2).
// R12 skeleton (512 thr, 4-row vertical) with cross-term plane deleted.
// out = 0.25 + sum_k clip(ssim_k, -1, 1) / 12

#define RAD 8
#define S 48            // smem tile cols: 32 + 2*RAD
#define TR 80           // smem tile rows: 64 + 2*RAD
#define NT 512
#define SSIM_C1 (0.01f*0.01f)
#define SSIM_C2 (0.03f*0.03f)

struct Weights {
    float2 h5[5],  v5[5];      // dup pairs (w,w); v normalized by center
    float2 h11[11], v11[11];
    float2 h17[17], v17[17];
};
__device__  Weights g_stage;
__constant__ Weights c_w;

union F2U { float2 f; unsigned long long u; };

__device__ __forceinline__ float2 ffma2(float2 a, float2 b, float2 c) {
    F2U A, B, C, D; A.f = a; B.f = b; C.f = c;
    asm("fma.rn.f32x2 %0, %1, %2, %3;" : "=l"(D.u) : "l"(A.u), "l"(B.u), "l"(C.u));
    return D.f;
}
__device__ __forceinline__ float2 fmul2(float2 a, float2 b) {
    F2U A, B, D; A.f = a; B.f = b;
    asm("mul.rn.f32x2 %0, %1, %2;" : "=l"(D.u) : "l"(A.u), "l"(B.u));
    return D.f;
}

__device__ __forceinline__ void build_tables(const float* g, int R,
                                             float2* h, float2* v) {
    const int K = 2*R + 1;
    float ctr = g[R*K + R];
    for (int t = 0; t < K; ++t) {
        float hv = g[R*K + t];
        float vv = g[t*K + R] / ctr;
        h[t] = make_float2(hv, hv);
        v[t] = make_float2(vv, vv);
    }
}

__global__ void prep_weights(const float* g5, const float* g11, const float* g17) {
    if (threadIdx.x != 0) return;
    build_tables(g5,  2, g_stage.h5,  g_stage.v5);
    build_tables(g11, 5, g_stage.h11, g_stage.v11);
    build_tables(g17, 8, g_stage.h17, g_stage.v17);
}

template<int R>
__device__ __forceinline__ void wpass(const float4* __restrict__ sT4,
                                      float2* __restrict__ HM,
                                      float2* __restrict__ HP,
                                      int tid, float acc[4])
{
    constexpr int K    = 2*R + 1;
    constexpr int ROWS = 64 + 2*R;
    constexpr int R0   = RAD - R;
    constexpr int NI   = ROWS * 16;
    constexpr int ODD  = ((RAD - R) & 1);
    constexpr int L    = (2*R + 2 + ODD + 1) / 2;   // float4 loads/item

    const float2* wh = (R == 2) ? c_w.h5 : (R == 5) ? c_w.h11 : c_w.h17;
    const float2* wv = (R == 2) ? c_w.v5 : (R == 5) ? c_w.v11 : c_w.v17;

    // ---- horizontal: 2 output cols/item, dense float4 sliding loads ----
    // Per tap: 1 fmul2 + up to 4 ffma2 (M=(mu_u,mu_d), P=(E[u^2],E[d^2])).
    #pragma unroll
    for (int it = 0; it < 3; ++it) {
        int i = tid + NT * it;
        if (i < NI) {
            int row = R0 + (i >> 4);
            int cg  = i & 15;
            const float4* p4 = sT4 + ((row * S + 2*cg + RAD - R - ODD) >> 1);
            float2 M0 = {0,0}, M1 = {0,0}, P0 = {0,0}, P1 = {0,0};

            auto tap = [&](float2 v, int t0) {
                if (t0 >= 0 && t0 <= K) {            // compile-time after unroll
                    float2 sq = fmul2(v, v);
                    if (t0 < K) {
                        float2 w = wh[t0];
                        M0 = ffma2(w, v,  M0);
                        P0 = ffma2(w, sq, P0);
                    }
                    if (t0 >= 1) {
                        float2 w = wh[t0 - 1];
                        M1 = ffma2(w, v,  M1);
                        P1 = ffma2(w, sq, P1);
                    }
                }
            };

            #pragma unroll
            for (int l = 0; l < L; ++l) {
                float4 q = p4[l];                    // LDS.128, dense
                tap(make_float2(q.x, q.y), 2*l - ODD);
                tap(make_float2(q.z, q.w), 2*l - ODD + 1);
            }

            int o = row * 32 + 2*cg;
            *reinterpret_cast<float4*>(HM + o) = make_float4(M0.x, M0.y, M1.x, M1.y);
            *reinterpret_cast<float4*>(HP + o) = make_float4(P0.x, P0.y, P1.x, P1.y);
        }
    }
    __syncthreads();

    // ---- vertical: 1 col x 4 rows per thread, all 512 threads (R12 shape) ----
    const int col = tid & 31;
    const int ty  = tid >> 5;                        // 0..15 -> rows 4ty..4ty+3
    float2 aM[4] = {}; float2 aP[4] = {};
    const int ybase = RAD + 4*ty - R;
    #pragma unroll
    for (int yy = 0; yy < 4 + 2*R; ++yy) {
        int o = (ybase + yy) * 32 + col;
        float2 hM = HM[o];
        float2 hP = HP[o];
        #pragma unroll
        for (int j = 0; j < 4; ++j) {
            int t = yy - j;
            if (t >= 0 && t < K) {
                float2 w = wv[t];
                aM[j] = ffma2(w, hM, aM[j]);
                aP[j] = ffma2(w, hP, aP[j]);
            }
        }
    }

    #pragma unroll
    for (int j = 0; j < 4; ++j) {
        float2 m2 = fmul2(aM[j], aM[j]);             // (mu_u^2, mu_d^2)
        float q      = (m2.x + m2.y) * 0.5f;         // mu1^2 + mu2^2
        float t2mu12 = (m2.x - m2.y) * 0.5f;         // 2*mu1*mu2
        float t2s12  = (aP[j].x - aP[j].y) * 0.5f - t2mu12;   // 2*sigma12
        float ssum   = (aP[j].x + aP[j].y) * 0.5f - q;        // s1sq + s2sq
        float num = (t2mu12 + SSIM_C1) * (t2s12 + SSIM_C2);
        float den = (q + SSIM_C1) * (ssum + SSIM_C2);
        float v = __fdividef(num, den);
        acc[j] += fminf(1.f, fmaxf(-1.f, v));
    }
    __syncthreads();   // single H buffer is reused by next window
}

__global__ __launch_bounds__(NT, 2)
void mssim_kernel(const float* __restrict__ b1,
                  const float* __restrict__ b2,
                  float* __restrict__ out)
{
    // dynamic smem: sT 30720 | HM 20480 | HP 20480 = 71680 B
    extern __shared__ __align__(16) char smbuf[];
    float2* sT = reinterpret_cast<float2*>(smbuf);
    float2* HM = reinterpret_cast<float2*>(smbuf + 30720);
    float2* HP = reinterpret_cast<float2*>(smbuf + 51200);

    const int tid = threadIdx.x;
    const int plane = blockIdx.z;
    const long base = (long)plane * (512 * 512);
    const int ox = blockIdx.x * 32 - RAD;
    const int oy = blockIdx.y * 64 - RAD;

    #pragma unroll
    for (int sIt = 0; sIt < 8; ++sIt) {
        int i = tid + NT * sIt;                // need 0..3839
        if (i < TR * S) {
            int ly = i / S;
            int lx = i - ly * S;
            int gy = oy + ly;
            int gx = ox + lx;
            float v1 = 0.f, v2 = 0.f;
            if (gy >= 0 && gy < 512 && gx >= 0 && gx < 512) {
                long idx = base + (long)gy * 512 + gx;
                v1 = b1[idx];
                v2 = b2[idx];
            }
            sT[i] = make_float2(v1 + v2, v1 - v2);   // (u, d)
        }
    }
    __syncthreads();

    const float4* sT4 = reinterpret_cast<const float4*>(smbuf);

    float acc[4] = {0.f, 0.f, 0.f, 0.f};
    wpass<2>(sT4, HM, HP, tid, acc);
    wpass<5>(sT4, HM, HP, tid, acc);
    wpass<8>(sT4, HM, HP, tid, acc);

    const int tx = tid & 31;
    const int ty = tid >> 5;
    const int gx = blockIdx.x * 32 + tx;
    #pragma unroll
    for (int j = 0; j < 4; ++j) {
        int gy = blockIdx.y * 64 + ty * 4 + j;
        out[base + (long)gy * 512 + gx] = 0.25f + acc[j] * (1.0f / 12.0f);
    }
}

extern "C" void kernel_launch(void* const* d_in, const int* in_sizes, int n_in,
                              void* d_out, int out_size) {
    const float* b1 = (const float*)d_in[0];
    const float* b2 = (const float*)d_in[1];

    prep_weights<<<1, 32>>>((const float*)d_in[2], (const float*)d_in[3],
                            (const float*)d_in[4]);
    void* stage_ptr = nullptr;
    cudaGetSymbolAddress(&stage_ptr, g_stage);
    cudaMemcpyToSymbolAsync(c_w, stage_ptr, sizeof(Weights), 0,
                            cudaMemcpyDeviceToDevice, 0);

    static bool attr_set = false;
    if (!attr_set) {
        cudaFuncSetAttribute(mssim_kernel,
                             cudaFuncAttributeMaxDynamicSharedMemorySize, 71680);
        attr_set = true;
    }

    dim3 grid(512 / 32, 512 / 64, 96);     // 16 x 8 x 96
    mssim_kernel<<<grid, NT, 71680>>>(b1, b2, (float*)d_out);
}